// round 3
// baseline (speedup 1.0000x reference)
#include <cuda_runtime.h>
#include <cuda_bf16.h>
#include <cstdint>

// Depthwise separable Gaussian blur, K=121, replicate padding.
// out = (x *row g1d) *col g1d, g1d normalized 1D Gaussian (exact separation
// of the reference's normalized 2D kernel).

#define IMGS   24          // 8 * 3
#define HW     512
#define IMG_PX (HW * HW)   // 262144
#define TAPS   121
#define TPAD   128         // taps padded with zeros to 128

__device__ float g_w[TPAD];                 // normalized 1D weights (zero-padded)
__device__ float g_tmp[IMGS * IMG_PX];      // horizontal-pass scratch (~25 MB)

// ---------------------------------------------------------------------------
// Weight prep: g[i] = exp(-(i-60)^2 / (2 var)), normalized; w[121..127] = 0.
// ---------------------------------------------------------------------------
__global__ void prep_kernel(const float* __restrict__ sigma) {
    __shared__ float g[TAPS];
    __shared__ float stot;
    const int i = threadIdx.x;  // 128 threads
    const float s   = sigma[0] * 8.0f + 16.0f;
    const float var = s * s;
    float val = 0.0f;
    if (i < TAPS) {
        const float d = (float)(i - 60);
        val = expf(-(d * d) / (2.0f * var));
        g[i] = val;
    }
    __syncthreads();
    if (i == 0) {
        float t = 0.0f;
        for (int q = 0; q < TAPS; ++q) t += g[q];
        stot = t;
    }
    __syncthreads();
    g_w[i] = (i < TAPS) ? (val / stot) : 0.0f;
}

// ---------------------------------------------------------------------------
// Pass 1: horizontal 121-tap conv. One block per (img,row); 64 threads;
// each thread computes 8 consecutive x with a 16-deep register ring.
// ---------------------------------------------------------------------------
#define ROWLEN 656   // 60 halo + 512 + padded tail (reads up to idx 647)

__global__ __launch_bounds__(64) void hpass_kernel(const float* __restrict__ x) {
    __shared__ float srow[ROWLEN];
    __shared__ float wsh[TPAD];
    const int t   = threadIdx.x;
    const int row = blockIdx.x;
    const int img = blockIdx.y;
    const float* src = x + ((size_t)img * HW + row) * HW;

    wsh[t]      = g_w[t];
    wsh[t + 64] = g_w[t + 64];
    #pragma unroll
    for (int i = t; i < ROWLEN; i += 64) {
        int xi = i - 60;
        xi = xi < 0 ? 0 : (xi > HW - 1 ? HW - 1 : xi);
        srow[i] = src[xi];
    }
    __syncthreads();

    const int x0 = t * 8;
    const float4* srow4 = (const float4*)srow;

    float buf[16];
    #pragma unroll
    for (int q = 0; q < 4; ++q) {
        float4 v = srow4[(x0 >> 2) + q];
        buf[q * 4 + 0] = v.x; buf[q * 4 + 1] = v.y;
        buf[q * 4 + 2] = v.z; buf[q * 4 + 3] = v.w;
    }
    float acc[8] = {0.f, 0.f, 0.f, 0.f, 0.f, 0.f, 0.f, 0.f};

    #pragma unroll 1
    for (int kb = 0; kb < 8; ++kb) {          // 8 x 16 = 128 taps (zero-padded)
        #pragma unroll
        for (int i = 0; i < 16; ++i) {
            const int k = kb * 16 + i;
            const float wk = wsh[k];
            #pragma unroll
            for (int j = 0; j < 8; ++j)
                acc[j] = fmaf(wk, buf[(i + j) & 15], acc[j]);
            if ((i & 3) == 3) {
                // refill: rows x0+k+13 .. x0+k+16 into ring (slots free after this tap)
                float4 v = srow4[(x0 + k + 13) >> 2];
                const int s0 = (i + 13) & 15;   // multiple of 4
                buf[s0 + 0] = v.x; buf[s0 + 1] = v.y;
                buf[s0 + 2] = v.z; buf[s0 + 3] = v.w;
            }
        }
    }

    float* dst = g_tmp + ((size_t)img * HW + row) * HW + x0;
    ((float4*)dst)[0] = make_float4(acc[0], acc[1], acc[2], acc[3]);
    ((float4*)dst)[1] = make_float4(acc[4], acc[5], acc[6], acc[7]);
}

// ---------------------------------------------------------------------------
// Pass 2: vertical 121-tap conv with packed fma.rn.f32x2 (2 x-columns/lane).
// Block: 32-col x 64-row output tile, 64 threads = 16 x-pairs x 4 y-groups,
// each thread computes 16 y outputs for its x-pair (16-deep f32x2 ring).
// smem tile: 192 rows x 32 cols (60 top halo + 64 + padded bottom).
// ---------------------------------------------------------------------------
#define TROWS 192
#define TCOLS 32

__global__ __launch_bounds__(64) void vpass_kernel(float* __restrict__ out) {
    __shared__ float tile[TROWS * TCOLS];
    __shared__ float wsh[TPAD];
    const int t     = threadIdx.x;
    const int img   = blockIdx.z;
    const int xbase = blockIdx.x * TCOLS;
    const int ybase = blockIdx.y * 64;
    const float* src = g_tmp + (size_t)img * IMG_PX;

    wsh[t]      = g_w[t];
    wsh[t + 64] = g_w[t + 64];

    // stage 192x32 tile (coalesced float4 rows, replicate-clamped in y)
    const int cx4 = t & 7;     // float4 column 0..7
    const int r0  = t >> 3;    // 0..7
    #pragma unroll
    for (int rr = 0; rr < TROWS; rr += 8) {
        const int r = rr + r0;
        int gy = ybase - 60 + r;
        gy = gy < 0 ? 0 : (gy > HW - 1 ? HW - 1 : gy);
        float4 v = ((const float4*)(src + (size_t)gy * HW + xbase))[cx4];
        ((float4*)tile)[r * 8 + cx4] = v;
    }
    __syncthreads();

    const int px = t & 15;          // x-pair 0..15 -> cols 2*px, 2*px+1
    const int yg = (t >> 4) * 16;   // y-group base: 0,16,32,48
    const unsigned long long* tile2 = (const unsigned long long*)tile; // 16 pairs/row

    unsigned long long buf[16];
    #pragma unroll
    for (int q = 0; q < 16; ++q) buf[q] = tile2[(yg + q) * 16 + px];
    unsigned long long acc[16];
    #pragma unroll
    for (int j = 0; j < 16; ++j) acc[j] = 0ULL;   // (+0.f, +0.f)

    #pragma unroll 1
    for (int kb = 0; kb < 8; ++kb) {
        #pragma unroll
        for (int i = 0; i < 16; ++i) {
            const int k = kb * 16 + i;
            const float wk = wsh[k];
            unsigned long long w2;
            asm("mov.b64 %0, {%1, %1};" : "=l"(w2) : "f"(wk));
            #pragma unroll
            for (int j = 0; j < 16; ++j)
                asm("fma.rn.f32x2 %0, %1, %2, %0;"
                    : "+l"(acc[j]) : "l"(buf[(i + j) & 15]), "l"(w2));
            buf[i] = tile2[(yg + k + 16) * 16 + px];   // slide window
        }
    }

    float* dstbase = out + (size_t)img * IMG_PX
                   + (size_t)(ybase + yg) * HW + xbase + px * 2;
    #pragma unroll
    for (int j = 0; j < 16; ++j) {
        const unsigned long long a = acc[j];
        float2 o;
        o.x = __uint_as_float((unsigned)(a & 0xffffffffu));
        o.y = __uint_as_float((unsigned)(a >> 32));
        *((float2*)(dstbase + (size_t)j * HW)) = o;
    }
}

// ---------------------------------------------------------------------------
extern "C" void kernel_launch(void* const* d_in, const int* in_sizes, int n_in,
                              void* d_out, int out_size) {
    const float* x     = (const float*)d_in[0];
    const float* sigma = (const float*)d_in[1];
    float* out = (float*)d_out;

    prep_kernel<<<1, 128>>>(sigma);
    hpass_kernel<<<dim3(HW, IMGS), 64>>>(x);
    vpass_kernel<<<dim3(HW / TCOLS, HW / 64, IMGS), 64>>>(out);
}